// round 2
// baseline (speedup 1.0000x reference)
#include <cuda_runtime.h>
#include <math_constants.h>

#define BB   16
#define NN   2048
#define KNB  20
#define BN   (BB*NN)        // 32768
#define PTS  32
#define NBLK (BN/PTS)       // 1024
#define CCAT 512

// ---------------- scratch (device globals; no allocation allowed) ----------
__device__ int   g_idx [BN*KNB];        // kNN indices (per-batch local)
__device__ float g_hcat[BN*CCAT];       // concatenated activations (B,N,512)
__device__ float g_pre [BN*256];        // pre-BN activations of current layer
__device__ float g_part[NBLK*256*2];    // per-block partial (sum, sumsq)
__device__ float g_mean[256];
__device__ float g_rstd[256];

// ---------------- kNN: top-20 by neg squared distance ----------------------
__global__ void __launch_bounds__(256) knn_kernel(const float* __restrict__ x)
{
    __shared__ float sx[NN*3];
    __shared__ float ssq[NN];
    const int b = blockIdx.y;
    const float* xb = x + (size_t)b*NN*3;
    for (int i = threadIdx.x; i < NN*3; i += 256) sx[i] = xb[i];
    __syncthreads();
    for (int i = threadIdx.x; i < NN; i += 256) {
        float a0 = sx[i*3], a1 = sx[i*3+1], a2 = sx[i*3+2];
        ssq[i] = a0*a0 + a1*a1 + a2*a2;
    }
    __syncthreads();
    const int n = blockIdx.x*256 + threadIdx.x;
    const float q0 = sx[n*3], q1 = sx[n*3+1], q2 = sx[n*3+2];
    const float sqn = ssq[n];

    float bv[KNB]; int bi[KNB];
    #pragma unroll
    for (int j = 0; j < KNB; ++j) { bv[j] = -CUDART_INF_F; bi[j] = 0; }

    for (int m = 0; m < NN; ++m) {
        float inner = q0*sx[m*3] + q1*sx[m*3+1] + q2*sx[m*3+2];
        float v = 2.f*inner - sqn - ssq[m];
        if (v > bv[KNB-1]) {
            // sorted (descending) insert; stable: equal values keep earlier index first
            #pragma unroll
            for (int j = KNB-1; j >= 1; --j) {
                bool shift = v > bv[j-1];
                float nv = shift ? bv[j-1] : v;
                int   ni = shift ? bi[j-1] : m;
                if (v > bv[j]) { bv[j] = nv; bi[j] = ni; }
            }
            if (v > bv[0]) { bv[0] = v; bi[0] = m; }
        }
    }
    int* out = g_idx + ((size_t)b*NN + n)*KNB;
    #pragma unroll
    for (int j = 0; j < KNB; ++j) out[j] = bi[j];
}

// ---------------- EdgeConv: pre-BN max over k + BN partial sums ------------
// (bias cancels under BN; max-over-k commutes with monotone BN+LReLU)
__global__ void __launch_bounds__(64) edge_kernel(const float* __restrict__ x,
                                                  const float* __restrict__ w_edge)
{
    __shared__ float s_nb[PTS][KNB][3];
    __shared__ float s_ctr[PTS][3];
    const int p0 = blockIdx.x * PTS;
    const int tid = threadIdx.x;

    for (int j = tid; j < PTS*KNB; j += 64) {
        int p = j / KNB, k = j - p*KNB;
        int gp = p0 + p;
        int bb = gp >> 11;                    // /NN
        int gi = g_idx[gp*KNB + k];
        const float* xp = x + ((size_t)bb*NN + gi)*3;
        s_nb[p][k][0] = xp[0]; s_nb[p][k][1] = xp[1]; s_nb[p][k][2] = xp[2];
    }
    if (tid < PTS) {
        int gp = p0 + tid;
        s_ctr[tid][0] = x[gp*3]; s_ctr[tid][1] = x[gp*3+1]; s_ctr[tid][2] = x[gp*3+2];
    }
    __syncthreads();

    const int o = tid;
    const float w0 = w_edge[o*6+0], w1 = w_edge[o*6+1], w2 = w_edge[o*6+2];
    const float w3 = w_edge[o*6+3], w4 = w_edge[o*6+4], w5 = w_edge[o*6+5];
    float s = 0.f, s2 = 0.f;
    for (int p = 0; p < PTS; ++p) {
        float c0 = s_ctr[p][0], c1 = s_ctr[p][1], c2 = s_ctr[p][2];
        float base = w3*c0 + w4*c1 + w5*c2;
        float mx = -CUDART_INF_F;
        #pragma unroll
        for (int k = 0; k < KNB; ++k) {
            float v = base + w0*(s_nb[p][k][0]-c0)
                           + w1*(s_nb[p][k][1]-c1)
                           + w2*(s_nb[p][k][2]-c2);
            mx = fmaxf(mx, v);
            s += v; s2 += v*v;
        }
        g_pre[(size_t)(p0+p)*64 + o] = mx;
    }
    g_part[(size_t)blockIdx.x*128 + o*2]     = s;
    g_part[(size_t)blockIdx.x*128 + o*2 + 1] = s2;
}

// ---------------- BN statistics finalize -----------------------------------
__global__ void stats_kernel(int O, float inv_count)
{
    int o = threadIdx.x;
    if (o >= O) return;
    double s = 0.0, s2 = 0.0;
    for (int bk = 0; bk < NBLK; ++bk) {
        s  += (double)g_part[(size_t)bk*O*2 + o*2];
        s2 += (double)g_part[(size_t)bk*O*2 + o*2 + 1];
    }
    double m   = s  * (double)inv_count;
    double var = s2 * (double)inv_count - m*m;
    g_mean[o] = (float)m;
    g_rstd[o] = rsqrtf((float)var + 1e-5f);
}

// ---------------- BN + LeakyReLU apply into hcat slice ---------------------
__global__ void __launch_bounds__(256) apply_kernel(int O, int off)
{
    int i = blockIdx.x*256 + threadIdx.x;
    int p = i / O, o = i - p*O;
    float v = (g_pre[i] - g_mean[o]) * g_rstd[o];
    g_hcat[(size_t)p*CCAT + off + o] = v > 0.f ? v : 0.2f*v;
}

// ---------------- graph-max-pool gather + 1x1 conv + BN partials -----------
template<int CIN, int COUT>
__global__ void __launch_bounds__(128) layer_kernel(const float* __restrict__ w, int off_in)
{
    __shared__ float s_g[PTS*CIN];
    __shared__ int   s_idx[PTS*KNB];
    const int tid = threadIdx.x;
    const int p0  = blockIdx.x * PTS;

    for (int j = tid; j < PTS*KNB; j += 128) s_idx[j] = g_idx[(size_t)p0*KNB + j];
    __syncthreads();

    // gather-max of previous activations into smem
    for (int v = tid; v < PTS*CIN; v += 128) {
        int p = v / CIN, c = v - p*CIN;
        int gp = p0 + p, bb = gp >> 11;
        const float* hb = g_hcat + (size_t)bb*NN*CCAT + off_in + c;
        float m = -CUDART_INF_F;
        #pragma unroll
        for (int j = 0; j < KNB; ++j)
            m = fmaxf(m, hb[(size_t)s_idx[p*KNB+j]*CCAT]);
        s_g[v] = m;
    }
    __syncthreads();

    // 1x1 conv: each thread owns channel(s) o across all 32 points
    #pragma unroll
    for (int rep = 0; rep < (COUT+127)/128; ++rep) {
        int o = tid + rep*128;
        if (o < COUT) {
            float acc[PTS];
            #pragma unroll
            for (int p = 0; p < PTS; ++p) acc[p] = 0.f;
            for (int c = 0; c < CIN; ++c) {
                float wv = w[o*CIN + c];
                #pragma unroll
                for (int p = 0; p < PTS; ++p)
                    acc[p] += wv * s_g[p*CIN + c];   // broadcast LDS
            }
            float s = 0.f, s2 = 0.f;
            #pragma unroll
            for (int p = 0; p < PTS; ++p) {
                float vv = acc[p];
                g_pre[(size_t)(p0+p)*COUT + o] = vv;
                s += vv; s2 += vv*vv;
            }
            g_part[(size_t)blockIdx.x*COUT*2 + o*2]     = s;
            g_part[(size_t)blockIdx.x*COUT*2 + o*2 + 1] = s2;
        }
    }
}

// ---------------- final 512->1024 GEMM fused with global max over N --------
__device__ __forceinline__ int fkey(float f) {
    int b = __float_as_int(f);
    return b >= 0 ? b : (b ^ 0x7FFFFFFF);   // order-preserving int mapping
}

__global__ void out_init(int* ok) {
    ok[blockIdx.x*256 + threadIdx.x] = fkey(-CUDART_INF_F);
}

__global__ void __launch_bounds__(256) final_kernel(const float* __restrict__ wf,
                                                    const float* __restrict__ bf,
                                                    int* __restrict__ okeys)
{
    __shared__ float sA[32*129];   // [kc][n_local], padded
    __shared__ float sB[32*65];    // [kc][o_local], padded
    __shared__ float sred[16*64];
    const int tid = threadIdx.x;
    const int tx = tid & 15, ty = tid >> 4;
    const int b = blockIdx.z, n0 = blockIdx.x*128, o0 = blockIdx.y*64;
    const float* Ab = g_hcat + ((size_t)b*NN + n0)*CCAT;
    const float* Bw = wf + (size_t)o0*CCAT;

    float acc[8][4];
    #pragma unroll
    for (int i = 0; i < 8; ++i)
        #pragma unroll
        for (int j = 0; j < 4; ++j) acc[i][j] = 0.f;

    for (int k0 = 0; k0 < CCAT; k0 += 32) {
        #pragma unroll
        for (int i = 0; i < 16; ++i) {
            int flat = tid + i*256; int kc = flat & 31, nl = flat >> 5;
            sA[kc*129 + nl] = Ab[(size_t)nl*CCAT + k0 + kc];
        }
        #pragma unroll
        for (int i = 0; i < 8; ++i) {
            int flat = tid + i*256; int kc = flat & 31, ol = flat >> 5;
            sB[kc*65 + ol] = Bw[(size_t)ol*CCAT + k0 + kc];
        }
        __syncthreads();
        #pragma unroll
        for (int kc = 0; kc < 32; ++kc) {
            float a[8], bb2[4];
            #pragma unroll
            for (int i = 0; i < 8; ++i) a[i] = sA[kc*129 + ty*8 + i];
            #pragma unroll
            for (int j = 0; j < 4; ++j) bb2[j] = sB[kc*65 + tx*4 + j];
            #pragma unroll
            for (int i = 0; i < 8; ++i)
                #pragma unroll
                for (int j = 0; j < 4; ++j) acc[i][j] += a[i]*bb2[j];
        }
        __syncthreads();
    }

    // max over this block's 128 rows, then atomic max into output
    #pragma unroll
    for (int j = 0; j < 4; ++j) {
        float m = acc[0][j];
        #pragma unroll
        for (int i = 1; i < 8; ++i) m = fmaxf(m, acc[i][j]);
        sred[ty*64 + tx*4 + j] = m;
    }
    __syncthreads();
    if (ty == 0) {
        #pragma unroll
        for (int j = 0; j < 4; ++j) {
            int c = tx*4 + j;
            float m = sred[c];
            for (int t = 1; t < 16; ++t) m = fmaxf(m, sred[t*64 + c]);
            m += bf[o0 + c];                         // bias commutes with max
            atomicMax(&okeys[b*1024 + o0 + c], fkey(m));
        }
    }
}

__global__ void out_convert(int* ok, float* out) {
    int i = blockIdx.x*256 + threadIdx.x;
    int k = ok[i];
    int bits = k >= 0 ? k : (k ^ 0x7FFFFFFF);
    out[i] = __int_as_float(bits);
}

// ---------------- launch ----------------------------------------------------
extern "C" void kernel_launch(void* const* d_in, const int* in_sizes, int n_in,
                              void* d_out, int out_size)
{
    const float* x      = (const float*)d_in[0];
    const float* w_edge = (const float*)d_in[1];
    const float* w1     = (const float*)d_in[3];
    const float* w2     = (const float*)d_in[5];
    const float* w3     = (const float*)d_in[7];
    const float* wf     = (const float*)d_in[9];
    const float* bf     = (const float*)d_in[10];

    knn_kernel<<<dim3(NN/256, BB), 256>>>(x);

    edge_kernel<<<NBLK, 64>>>(x, w_edge);
    stats_kernel<<<1, 64>>>(64, 1.f/(float)(BN*KNB));
    apply_kernel<<<BN*64/256, 256>>>(64, 0);

    layer_kernel<64,64><<<NBLK, 128>>>(w1, 0);
    stats_kernel<<<1, 64>>>(64, 1.f/(float)BN);
    apply_kernel<<<BN*64/256, 256>>>(64, 64);

    layer_kernel<64,128><<<NBLK, 128>>>(w2, 64);
    stats_kernel<<<1, 128>>>(128, 1.f/(float)BN);
    apply_kernel<<<BN*128/256, 256>>>(128, 128);

    layer_kernel<128,256><<<NBLK, 128>>>(w3, 128);
    stats_kernel<<<1, 256>>>(256, 1.f/(float)BN);
    apply_kernel<<<BN*256/256, 256>>>(256, 256);

    out_init<<<out_size/256, 256>>>((int*)d_out);
    final_kernel<<<dim3(16,16,16), 256>>>(wf, bf, (int*)d_out);
    out_convert<<<out_size/256, 256>>>((int*)d_out, (float*)d_out);
}

// round 3
// speedup vs baseline: 1.0308x; 1.0308x over previous
#include <cuda_runtime.h>
#include <math_constants.h>

#define BB   16
#define NN   2048
#define KNB  20
#define BN   (BB*NN)        // 32768
#define PTS  32
#define NBLK (BN/PTS)       // 1024
#define CCAT 512

// ---------------- scratch (device globals; no allocation allowed) ----------
__device__ int   g_idx [BN*KNB];        // kNN indices (per-batch local)
__device__ float g_hcat[BN*CCAT];       // concatenated activations (B,N,512)
__device__ float g_pre [BN*256];        // pre-BN activations of current layer
__device__ float g_part[NBLK*256*2];    // per-block partial (sum, sumsq)
__device__ float g_mean[256];
__device__ float g_rstd[256];

// ---------------- packed f32x2 helpers (Blackwell FFMA2 path) --------------
typedef unsigned long long u64;

__device__ __forceinline__ u64 pack_dup(float v) {
    u64 d;
    unsigned r = __float_as_uint(v);
    asm("mov.b64 %0, {%1, %1};" : "=l"(d) : "r"(r));
    return d;
}
__device__ __forceinline__ u64 ffma2(u64 a, u64 b, u64 c) {
    u64 d;
    asm("fma.rn.f32x2 %0, %1, %2, %3;" : "=l"(d) : "l"(a), "l"(b), "l"(c));
    return d;
}
__device__ __forceinline__ float lo32(u64 v) { return __uint_as_float((unsigned)v); }
__device__ __forceinline__ float hi32(u64 v) { return __uint_as_float((unsigned)(v >> 32)); }

// ---------------- kNN: top-20 by neg squared distance ----------------------
__global__ void __launch_bounds__(256) knn_kernel(const float* __restrict__ x)
{
    __shared__ float sx[NN*3];
    __shared__ float ssq[NN];
    const int b = blockIdx.y;
    const float* xb = x + (size_t)b*NN*3;
    for (int i = threadIdx.x; i < NN*3; i += 256) sx[i] = xb[i];
    __syncthreads();
    for (int i = threadIdx.x; i < NN; i += 256) {
        float a0 = sx[i*3], a1 = sx[i*3+1], a2 = sx[i*3+2];
        ssq[i] = a0*a0 + a1*a1 + a2*a2;
    }
    __syncthreads();
    const int n = blockIdx.x*256 + threadIdx.x;
    const float q0 = sx[n*3], q1 = sx[n*3+1], q2 = sx[n*3+2];
    const float sqn = ssq[n];

    float bv[KNB]; int bi[KNB];
    #pragma unroll
    for (int j = 0; j < KNB; ++j) { bv[j] = -CUDART_INF_F; bi[j] = 0; }

    for (int m = 0; m < NN; ++m) {
        float inner = q0*sx[m*3] + q1*sx[m*3+1] + q2*sx[m*3+2];
        float v = 2.f*inner - sqn - ssq[m];
        if (v > bv[KNB-1]) {
            #pragma unroll
            for (int j = KNB-1; j >= 1; --j) {
                bool shift = v > bv[j-1];
                float nv = shift ? bv[j-1] : v;
                int   ni = shift ? bi[j-1] : m;
                if (v > bv[j]) { bv[j] = nv; bi[j] = ni; }
            }
            if (v > bv[0]) { bv[0] = v; bi[0] = m; }
        }
    }
    int* out = g_idx + ((size_t)b*NN + n)*KNB;
    #pragma unroll
    for (int j = 0; j < KNB; ++j) out[j] = bi[j];
}

// ---------------- EdgeConv: pre-BN max over k + BN partial sums ------------
__global__ void __launch_bounds__(64) edge_kernel(const float* __restrict__ x,
                                                  const float* __restrict__ w_edge)
{
    __shared__ float s_nb[PTS][KNB][3];
    __shared__ float s_ctr[PTS][3];
    const int p0 = blockIdx.x * PTS;
    const int tid = threadIdx.x;

    for (int j = tid; j < PTS*KNB; j += 64) {
        int p = j / KNB, k = j - p*KNB;
        int gp = p0 + p;
        int bb = gp >> 11;
        int gi = g_idx[gp*KNB + k];
        const float* xp = x + ((size_t)bb*NN + gi)*3;
        s_nb[p][k][0] = xp[0]; s_nb[p][k][1] = xp[1]; s_nb[p][k][2] = xp[2];
    }
    if (tid < PTS) {
        int gp = p0 + tid;
        s_ctr[tid][0] = x[gp*3]; s_ctr[tid][1] = x[gp*3+1]; s_ctr[tid][2] = x[gp*3+2];
    }
    __syncthreads();

    const int o = tid;
    const float w0 = w_edge[o*6+0], w1 = w_edge[o*6+1], w2 = w_edge[o*6+2];
    const float w3 = w_edge[o*6+3], w4 = w_edge[o*6+4], w5 = w_edge[o*6+5];
    float s = 0.f, s2 = 0.f;
    for (int p = 0; p < PTS; ++p) {
        float c0 = s_ctr[p][0], c1 = s_ctr[p][1], c2 = s_ctr[p][2];
        float base = w3*c0 + w4*c1 + w5*c2;
        float mx = -CUDART_INF_F;
        #pragma unroll
        for (int k = 0; k < KNB; ++k) {
            float v = base + w0*(s_nb[p][k][0]-c0)
                           + w1*(s_nb[p][k][1]-c1)
                           + w2*(s_nb[p][k][2]-c2);
            mx = fmaxf(mx, v);
            s += v; s2 += v*v;
        }
        g_pre[(size_t)(p0+p)*64 + o] = mx;
    }
    g_part[(size_t)blockIdx.x*128 + o*2]     = s;
    g_part[(size_t)blockIdx.x*128 + o*2 + 1] = s2;
}

// ---------------- BN statistics finalize -----------------------------------
__global__ void stats_kernel(int O, float inv_count)
{
    int o = threadIdx.x;
    if (o >= O) return;
    double s = 0.0, s2 = 0.0;
    for (int bk = 0; bk < NBLK; ++bk) {
        s  += (double)g_part[(size_t)bk*O*2 + o*2];
        s2 += (double)g_part[(size_t)bk*O*2 + o*2 + 1];
    }
    double m   = s  * (double)inv_count;
    double var = s2 * (double)inv_count - m*m;
    g_mean[o] = (float)m;
    g_rstd[o] = rsqrtf((float)var + 1e-5f);
}

// ---------------- BN + LeakyReLU apply into hcat slice ---------------------
__global__ void __launch_bounds__(256) apply_kernel(int O, int off)
{
    int i = blockIdx.x*256 + threadIdx.x;
    int p = i / O, o = i - p*O;
    float v = (g_pre[i] - g_mean[o]) * g_rstd[o];
    g_hcat[(size_t)p*CCAT + off + o] = v > 0.f ? v : 0.2f*v;
}

// ---------------- graph-max-pool gather + 1x1 conv + BN partials -----------
template<int CIN, int COUT>
__global__ void __launch_bounds__(128) layer_kernel(const float* __restrict__ w, int off_in)
{
    __shared__ float s_g[PTS*CIN];
    __shared__ int   s_idx[PTS*KNB];
    const int tid = threadIdx.x;
    const int p0  = blockIdx.x * PTS;

    for (int j = tid; j < PTS*KNB; j += 128) s_idx[j] = g_idx[(size_t)p0*KNB + j];
    __syncthreads();

    for (int v = tid; v < PTS*CIN; v += 128) {
        int p = v / CIN, c = v - p*CIN;
        int gp = p0 + p, bb = gp >> 11;
        const float* hb = g_hcat + (size_t)bb*NN*CCAT + off_in + c;
        float m = -CUDART_INF_F;
        #pragma unroll
        for (int j = 0; j < KNB; ++j)
            m = fmaxf(m, hb[(size_t)s_idx[p*KNB+j]*CCAT]);
        s_g[v] = m;
    }
    __syncthreads();

    #pragma unroll
    for (int rep = 0; rep < (COUT+127)/128; ++rep) {
        int o = tid + rep*128;
        if (o < COUT) {
            float acc[PTS];
            #pragma unroll
            for (int p = 0; p < PTS; ++p) acc[p] = 0.f;
            for (int c = 0; c < CIN; ++c) {
                float wv = w[o*CIN + c];
                #pragma unroll
                for (int p = 0; p < PTS; ++p)
                    acc[p] += wv * s_g[p*CIN + c];
            }
            float s = 0.f, s2 = 0.f;
            #pragma unroll
            for (int p = 0; p < PTS; ++p) {
                float vv = acc[p];
                g_pre[(size_t)(p0+p)*COUT + o] = vv;
                s += vv; s2 += vv*vv;
            }
            g_part[(size_t)blockIdx.x*COUT*2 + o*2]     = s;
            g_part[(size_t)blockIdx.x*COUT*2 + o*2 + 1] = s2;
        }
    }
}

// ---------------- final 512->1024 GEMM fused with global max over N --------
__device__ __forceinline__ int fkey(float f) {
    int b = __float_as_int(f);
    return b >= 0 ? b : (b ^ 0x7FFFFFFF);
}

__global__ void out_init(int* ok) {
    ok[blockIdx.x*256 + threadIdx.x] = fkey(-CUDART_INF_F);
}

#define SA_STRIDE 130   // even -> 8B-aligned paired rows; 2-way conflict on store only

__global__ void __launch_bounds__(256) final_kernel(const float* __restrict__ wf,
                                                    const float* __restrict__ bf,
                                                    int* __restrict__ okeys)
{
    __shared__ __align__(16) float sA[32*SA_STRIDE];  // [kc][n_local]
    __shared__ float sB[32*65];                        // [kc][o_local]
    __shared__ float sred[16*64];
    const int tid = threadIdx.x;
    const int tx = tid & 15, ty = tid >> 4;
    const int b = blockIdx.z, n0 = blockIdx.x*128, o0 = blockIdx.y*64;
    const float* Ab = g_hcat + ((size_t)b*NN + n0)*CCAT;
    const float* Bw = wf + (size_t)o0*CCAT;

    // acc2[p][j]: packed pair (row 2p, row 2p+1) for output column j
    u64 acc2[4][4];
    #pragma unroll
    for (int p = 0; p < 4; ++p)
        #pragma unroll
        for (int j = 0; j < 4; ++j) acc2[p][j] = 0ull;

    for (int k0 = 0; k0 < CCAT; k0 += 32) {
        #pragma unroll
        for (int i = 0; i < 16; ++i) {
            int flat = tid + i*256; int kc = flat & 31, nl = flat >> 5;
            sA[kc*SA_STRIDE + nl] = Ab[(size_t)nl*CCAT + k0 + kc];
        }
        #pragma unroll
        for (int i = 0; i < 8; ++i) {
            int flat = tid + i*256; int kc = flat & 31, ol = flat >> 5;
            sB[kc*65 + ol] = Bw[(size_t)ol*CCAT + k0 + kc];
        }
        __syncthreads();
        #pragma unroll
        for (int kc = 0; kc < 32; ++kc) {
            // A: 4 free paired loads (LDS.64); B: 4 scalars duplicated into pairs
            u64 a2[4];
            #pragma unroll
            for (int p = 0; p < 4; ++p)
                a2[p] = *reinterpret_cast<const u64*>(&sA[kc*SA_STRIDE + ty*8 + 2*p]);
            u64 b2[4];
            #pragma unroll
            for (int j = 0; j < 4; ++j)
                b2[j] = pack_dup(sB[kc*65 + tx*4 + j]);
            #pragma unroll
            for (int p = 0; p < 4; ++p)
                #pragma unroll
                for (int j = 0; j < 4; ++j)
                    acc2[p][j] = ffma2(a2[p], b2[j], acc2[p][j]);
        }
        __syncthreads();
    }

    // max over this block's 128 rows, then atomic max into output
    #pragma unroll
    for (int j = 0; j < 4; ++j) {
        float m = fmaxf(lo32(acc2[0][j]), hi32(acc2[0][j]));
        #pragma unroll
        for (int p = 1; p < 4; ++p)
            m = fmaxf(m, fmaxf(lo32(acc2[p][j]), hi32(acc2[p][j])));
        sred[ty*64 + tx*4 + j] = m;
    }
    __syncthreads();
    if (ty == 0) {
        #pragma unroll
        for (int j = 0; j < 4; ++j) {
            int c = tx*4 + j;
            float m = sred[c];
            for (int t = 1; t < 16; ++t) m = fmaxf(m, sred[t*64 + c]);
            m += bf[o0 + c];
            atomicMax(&okeys[b*1024 + o0 + c], fkey(m));
        }
    }
}

__global__ void out_convert(int* ok, float* out) {
    int i = blockIdx.x*256 + threadIdx.x;
    int k = ok[i];
    int bits = k >= 0 ? k : (k ^ 0x7FFFFFFF);
    out[i] = __int_as_float(bits);
}

// ---------------- launch ----------------------------------------------------
extern "C" void kernel_launch(void* const* d_in, const int* in_sizes, int n_in,
                              void* d_out, int out_size)
{
    const float* x      = (const float*)d_in[0];
    const float* w_edge = (const float*)d_in[1];
    const float* w1     = (const float*)d_in[3];
    const float* w2     = (const float*)d_in[5];
    const float* w3     = (const float*)d_in[7];
    const float* wf     = (const float*)d_in[9];
    const float* bf     = (const float*)d_in[10];

    knn_kernel<<<dim3(NN/256, BB), 256>>>(x);

    edge_kernel<<<NBLK, 64>>>(x, w_edge);
    stats_kernel<<<1, 64>>>(64, 1.f/(float)(BN*KNB));
    apply_kernel<<<BN*64/256, 256>>>(64, 0);

    layer_kernel<64,64><<<NBLK, 128>>>(w1, 0);
    stats_kernel<<<1, 64>>>(64, 1.f/(float)BN);
    apply_kernel<<<BN*64/256, 256>>>(64, 64);

    layer_kernel<64,128><<<NBLK, 128>>>(w2, 64);
    stats_kernel<<<1, 128>>>(128, 1.f/(float)BN);
    apply_kernel<<<BN*128/256, 256>>>(128, 128);

    layer_kernel<128,256><<<NBLK, 128>>>(w3, 128);
    stats_kernel<<<1, 256>>>(256, 1.f/(float)BN);
    apply_kernel<<<BN*256/256, 256>>>(256, 256);

    out_init<<<out_size/256, 256>>>((int*)d_out);
    final_kernel<<<dim3(16,16,16), 256>>>(wf, bf, (int*)d_out);
    out_convert<<<out_size/256, 256>>>((int*)d_out, (float*)d_out);
}

// round 4
// speedup vs baseline: 2.3165x; 2.2472x over previous
#include <cuda_runtime.h>
#include <math_constants.h>

#define BB   16
#define NN   2048
#define KNB  20
#define BN   (BB*NN)        // 32768
#define PTS  32
#define NBLK (BN/PTS)       // 1024
#define CCAT 512

// ---------------- scratch (device globals; no allocation allowed) ----------
__device__ int   g_idx [BN*KNB];        // kNN indices (per-batch local)
__device__ float g_hcat[BN*CCAT];       // concatenated activations (B,N,512)
__device__ float g_pre [BN*256];        // pre-BN activations of current layer
__device__ float g_part[NBLK*256*2];    // per-block partial (sum, sumsq)
__device__ float g_mean[256];
__device__ float g_rstd[256];

// ---------------- kNN: top-20 by neg squared distance ----------------------
__global__ void __launch_bounds__(256) knn_kernel(const float* __restrict__ x)
{
    __shared__ float sx[NN*3];
    __shared__ float ssq[NN];
    const int b = blockIdx.y;
    const float* xb = x + (size_t)b*NN*3;
    for (int i = threadIdx.x; i < NN*3; i += 256) sx[i] = xb[i];
    __syncthreads();
    for (int i = threadIdx.x; i < NN; i += 256) {
        float a0 = sx[i*3], a1 = sx[i*3+1], a2 = sx[i*3+2];
        ssq[i] = a0*a0 + a1*a1 + a2*a2;
    }
    __syncthreads();
    const int n = blockIdx.x*256 + threadIdx.x;
    const float q0 = sx[n*3], q1 = sx[n*3+1], q2 = sx[n*3+2];
    const float sqn = ssq[n];

    float bv[KNB]; int bi[KNB];
    #pragma unroll
    for (int j = 0; j < KNB; ++j) { bv[j] = -CUDART_INF_F; bi[j] = 0; }

    for (int m = 0; m < NN; ++m) {
        float inner = q0*sx[m*3] + q1*sx[m*3+1] + q2*sx[m*3+2];
        float v = 2.f*inner - sqn - ssq[m];
        if (v > bv[KNB-1]) {
            #pragma unroll
            for (int j = KNB-1; j >= 1; --j) {
                bool shift = v > bv[j-1];
                float nv = shift ? bv[j-1] : v;
                int   ni = shift ? bi[j-1] : m;
                if (v > bv[j]) { bv[j] = nv; bi[j] = ni; }
            }
            if (v > bv[0]) { bv[0] = v; bi[0] = m; }
        }
    }
    int* out = g_idx + ((size_t)b*NN + n)*KNB;
    #pragma unroll
    for (int j = 0; j < KNB; ++j) out[j] = bi[j];
}

// ---------------- EdgeConv: pre-BN max over k + BN partial sums ------------
__global__ void __launch_bounds__(64) edge_kernel(const float* __restrict__ x,
                                                  const float* __restrict__ w_edge)
{
    __shared__ float s_nb[PTS][KNB][3];
    __shared__ float s_ctr[PTS][3];
    const int p0 = blockIdx.x * PTS;
    const int tid = threadIdx.x;

    for (int j = tid; j < PTS*KNB; j += 64) {
        int p = j / KNB, k = j - p*KNB;
        int gp = p0 + p;
        int bb = gp >> 11;
        int gi = g_idx[gp*KNB + k];
        const float* xp = x + ((size_t)bb*NN + gi)*3;
        s_nb[p][k][0] = xp[0]; s_nb[p][k][1] = xp[1]; s_nb[p][k][2] = xp[2];
    }
    if (tid < PTS) {
        int gp = p0 + tid;
        s_ctr[tid][0] = x[gp*3]; s_ctr[tid][1] = x[gp*3+1]; s_ctr[tid][2] = x[gp*3+2];
    }
    __syncthreads();

    const int o = tid;
    const float w0 = w_edge[o*6+0], w1 = w_edge[o*6+1], w2 = w_edge[o*6+2];
    const float w3 = w_edge[o*6+3], w4 = w_edge[o*6+4], w5 = w_edge[o*6+5];
    float s = 0.f, s2 = 0.f;
    for (int p = 0; p < PTS; ++p) {
        float c0 = s_ctr[p][0], c1 = s_ctr[p][1], c2 = s_ctr[p][2];
        float base = w3*c0 + w4*c1 + w5*c2;
        float mx = -CUDART_INF_F;
        #pragma unroll
        for (int k = 0; k < KNB; ++k) {
            float v = base + w0*(s_nb[p][k][0]-c0)
                           + w1*(s_nb[p][k][1]-c1)
                           + w2*(s_nb[p][k][2]-c2);
            mx = fmaxf(mx, v);
            s += v; s2 += v*v;
        }
        g_pre[(size_t)(p0+p)*64 + o] = mx;
    }
    g_part[(size_t)blockIdx.x*128 + o*2]     = s;
    g_part[(size_t)blockIdx.x*128 + o*2 + 1] = s2;
}

// ---------------- BN statistics finalize (parallel: 1 block per channel) ---
__global__ void __launch_bounds__(256) stats_kernel(int O, float inv_count)
{
    __shared__ float rs[256], rs2[256];
    const int o = blockIdx.x;
    const int t = threadIdx.x;
    float s = 0.f, s2 = 0.f;
    for (int bk = t; bk < NBLK; bk += 256) {
        s  += g_part[(size_t)bk*O*2 + o*2];
        s2 += g_part[(size_t)bk*O*2 + o*2 + 1];
    }
    rs[t] = s; rs2[t] = s2;
    __syncthreads();
    for (int w = 128; w >= 1; w >>= 1) {
        if (t < w) { rs[t] += rs[t+w]; rs2[t] += rs2[t+w]; }
        __syncthreads();
    }
    if (t == 0) {
        float m   = rs[0]  * inv_count;
        float var = rs2[0] * inv_count - m*m;
        g_mean[o] = m;
        g_rstd[o] = rsqrtf(var + 1e-5f);
    }
}

// ---------------- BN + LeakyReLU apply into hcat slice ---------------------
__global__ void __launch_bounds__(256) apply_kernel(int O, int off)
{
    int i = blockIdx.x*256 + threadIdx.x;
    int p = i / O, o = i - p*O;
    float v = (g_pre[i] - g_mean[o]) * g_rstd[o];
    g_hcat[(size_t)p*CCAT + off + o] = v > 0.f ? v : 0.2f*v;
}

// ---------------- graph-max-pool gather + 1x1 conv + BN partials -----------
template<int CIN, int COUT>
__global__ void __launch_bounds__(128) layer_kernel(const float* __restrict__ w, int off_in)
{
    __shared__ float s_g[PTS*CIN];
    __shared__ int   s_idx[PTS*KNB];
    const int tid = threadIdx.x;
    const int p0  = blockIdx.x * PTS;

    for (int j = tid; j < PTS*KNB; j += 128) s_idx[j] = g_idx[(size_t)p0*KNB + j];
    __syncthreads();

    for (int v = tid; v < PTS*CIN; v += 128) {
        int p = v / CIN, c = v - p*CIN;
        int gp = p0 + p, bb = gp >> 11;
        const float* hb = g_hcat + (size_t)bb*NN*CCAT + off_in + c;
        float m = -CUDART_INF_F;
        #pragma unroll
        for (int j = 0; j < KNB; ++j)
            m = fmaxf(m, hb[(size_t)s_idx[p*KNB+j]*CCAT]);
        s_g[v] = m;
    }
    __syncthreads();

    #pragma unroll
    for (int rep = 0; rep < (COUT+127)/128; ++rep) {
        int o = tid + rep*128;
        if (o < COUT) {
            float acc[PTS];
            #pragma unroll
            for (int p = 0; p < PTS; ++p) acc[p] = 0.f;
            for (int c = 0; c < CIN; ++c) {
                float wv = w[o*CIN + c];
                #pragma unroll
                for (int p = 0; p < PTS; ++p)
                    acc[p] += wv * s_g[p*CIN + c];
            }
            float s = 0.f, s2 = 0.f;
            #pragma unroll
            for (int p = 0; p < PTS; ++p) {
                float vv = acc[p];
                g_pre[(size_t)(p0+p)*COUT + o] = vv;
                s += vv; s2 += vv*vv;
            }
            g_part[(size_t)blockIdx.x*COUT*2 + o*2]     = s;
            g_part[(size_t)blockIdx.x*COUT*2 + o*2 + 1] = s2;
        }
    }
}

// ---------------- final 512->1024 GEMM (tf32 tensor cores) + global max ----
__device__ __forceinline__ int fkey(float f) {
    int b = __float_as_int(f);
    return b >= 0 ? b : (b ^ 0x7FFFFFFF);
}

__global__ void out_init(int* ok) {
    ok[blockIdx.x*256 + threadIdx.x] = fkey(-CUDART_INF_F);
}

__device__ __forceinline__ unsigned cvt_tf32(float x) {
    unsigned u;
    asm("cvt.rna.tf32.f32 %0, %1;" : "=r"(u) : "f"(x));
    return u;
}

#define AST 36   // smem row stride (floats): bank = (4g+tig)%32 -> conflict-free frags

__global__ void __launch_bounds__(256) final_kernel(const float* __restrict__ wf,
                                                    const float* __restrict__ bf,
                                                    int* __restrict__ okeys)
{
    __shared__ float sA[128*AST];   // [row][k] A tile 128x32 (tf32-rounded)
    __shared__ float sB[64*AST];    // [o]  [k] B tile 64x32
    __shared__ float sred[8][16];

    const int tid  = threadIdx.x;
    const int lane = tid & 31, w = tid >> 5;
    const int g = lane >> 2, tig = lane & 3;
    const int wm = w & 1, wn = w >> 1;           // warp tile: 64 rows x 16 cols
    const int b = blockIdx.z, n0 = blockIdx.x*128, o0 = blockIdx.y*64;
    const float* Ab = g_hcat + ((size_t)b*NN + n0)*CCAT;
    const float* Bw = wf + (size_t)o0*CCAT;

    float acc[4][2][4];
    #pragma unroll
    for (int mi = 0; mi < 4; ++mi)
        #pragma unroll
        for (int ni = 0; ni < 2; ++ni)
            #pragma unroll
            for (int j = 0; j < 4; ++j) acc[mi][ni][j] = 0.f;

    const int srow = tid >> 3;        // 0..31
    const int skq  = (tid & 7) * 4;   // 0,4,...,28

    for (int k0 = 0; k0 < CCAT; k0 += 32) {
        // stage A (128x32) and B (64x32), rounding to tf32 once here
        #pragma unroll
        for (int it = 0; it < 4; ++it) {
            int r = srow + it*32;
            float4 v = *reinterpret_cast<const float4*>(&Ab[(size_t)r*CCAT + k0 + skq]);
            float* d = &sA[r*AST + skq];
            d[0] = __uint_as_float(cvt_tf32(v.x));
            d[1] = __uint_as_float(cvt_tf32(v.y));
            d[2] = __uint_as_float(cvt_tf32(v.z));
            d[3] = __uint_as_float(cvt_tf32(v.w));
        }
        #pragma unroll
        for (int it = 0; it < 2; ++it) {
            int r = srow + it*32;
            float4 v = *reinterpret_cast<const float4*>(&Bw[(size_t)r*CCAT + k0 + skq]);
            float* d = &sB[r*AST + skq];
            d[0] = __uint_as_float(cvt_tf32(v.x));
            d[1] = __uint_as_float(cvt_tf32(v.y));
            d[2] = __uint_as_float(cvt_tf32(v.z));
            d[3] = __uint_as_float(cvt_tf32(v.w));
        }
        __syncthreads();

        #pragma unroll
        for (int k8 = 0; k8 < 4; ++k8) {
            const int kk = k8*8;
            unsigned a0[4], a1[4], a2[4], a3[4];
            #pragma unroll
            for (int mi = 0; mi < 4; ++mi) {
                int r = wm*64 + mi*16 + g;
                a0[mi] = __float_as_uint(sA[r*AST      + kk + tig]);
                a1[mi] = __float_as_uint(sA[(r+8)*AST  + kk + tig]);
                a2[mi] = __float_as_uint(sA[r*AST      + kk + tig + 4]);
                a3[mi] = __float_as_uint(sA[(r+8)*AST  + kk + tig + 4]);
            }
            unsigned b0[2], b1[2];
            #pragma unroll
            for (int ni = 0; ni < 2; ++ni) {
                int c = wn*16 + ni*8 + g;
                b0[ni] = __float_as_uint(sB[c*AST + kk + tig]);
                b1[ni] = __float_as_uint(sB[c*AST + kk + tig + 4]);
            }
            #pragma unroll
            for (int mi = 0; mi < 4; ++mi)
                #pragma unroll
                for (int ni = 0; ni < 2; ++ni) {
                    float* c = acc[mi][ni];
                    asm("mma.sync.aligned.m16n8k8.row.col.f32.tf32.tf32.f32 "
                        "{%0,%1,%2,%3}, {%4,%5,%6,%7}, {%8,%9}, {%0,%1,%2,%3};"
                        : "+f"(c[0]), "+f"(c[1]), "+f"(c[2]), "+f"(c[3])
                        : "r"(a0[mi]), "r"(a1[mi]), "r"(a2[mi]), "r"(a3[mi]),
                          "r"(b0[ni]), "r"(b1[ni]));
                }
        }
        __syncthreads();
    }

    // ---- max over the 128 rows of this block's tile ----
    // acc[mi][ni][{0,2}] -> col tig*2, acc[mi][ni][{1,3}] -> col tig*2+1
    #pragma unroll
    for (int ni = 0; ni < 2; ++ni) {
        float m0 = -CUDART_INF_F, m1 = -CUDART_INF_F;
        #pragma unroll
        for (int mi = 0; mi < 4; ++mi) {
            m0 = fmaxf(m0, fmaxf(acc[mi][ni][0], acc[mi][ni][2]));
            m1 = fmaxf(m1, fmaxf(acc[mi][ni][1], acc[mi][ni][3]));
        }
        // reduce over g (lanes differing in bits 2..4)
        #pragma unroll
        for (int sh = 4; sh <= 16; sh <<= 1) {
            m0 = fmaxf(m0, __shfl_xor_sync(0xffffffffu, m0, sh));
            m1 = fmaxf(m1, __shfl_xor_sync(0xffffffffu, m1, sh));
        }
        if (g == 0) {
            sred[w][ni*8 + tig*2]     = m0;
            sred[w][ni*8 + tig*2 + 1] = m1;
        }
    }
    __syncthreads();
    if (tid < 64) {
        int cwn = tid >> 4, c16 = tid & 15;
        float m = fmaxf(sred[cwn*2][c16], sred[cwn*2+1][c16]);
        int oc = o0 + cwn*16 + c16;
        m += bf[oc];                      // bias commutes with max over n
        atomicMax(&okeys[b*1024 + oc], fkey(m));
    }
}

__global__ void out_convert(int* ok, float* out) {
    int i = blockIdx.x*256 + threadIdx.x;
    int k = ok[i];
    int bits = k >= 0 ? k : (k ^ 0x7FFFFFFF);
    out[i] = __int_as_float(bits);
}

// ---------------- launch ----------------------------------------------------
extern "C" void kernel_launch(void* const* d_in, const int* in_sizes, int n_in,
                              void* d_out, int out_size)
{
    const float* x      = (const float*)d_in[0];
    const float* w_edge = (const float*)d_in[1];
    const float* w1     = (const float*)d_in[3];
    const float* w2     = (const float*)d_in[5];
    const float* w3     = (const float*)d_in[7];
    const float* wf     = (const float*)d_in[9];
    const float* bf     = (const float*)d_in[10];

    knn_kernel<<<dim3(NN/256, BB), 256>>>(x);

    edge_kernel<<<NBLK, 64>>>(x, w_edge);
    stats_kernel<<<64, 256>>>(64, 1.f/(float)(BN*KNB));
    apply_kernel<<<BN*64/256, 256>>>(64, 0);

    layer_kernel<64,64><<<NBLK, 128>>>(w1, 0);
    stats_kernel<<<64, 256>>>(64, 1.f/(float)BN);
    apply_kernel<<<BN*64/256, 256>>>(64, 64);

    layer_kernel<64,128><<<NBLK, 128>>>(w2, 64);
    stats_kernel<<<128, 256>>>(128, 1.f/(float)BN);
    apply_kernel<<<BN*128/256, 256>>>(128, 128);

    layer_kernel<128,256><<<NBLK, 128>>>(w3, 128);
    stats_kernel<<<256, 256>>>(256, 1.f/(float)BN);
    apply_kernel<<<BN*256/256, 256>>>(256, 256);

    out_init<<<out_size/256, 256>>>((int*)d_out);
    final_kernel<<<dim3(16,16,16), 256>>>(wf, bf, (int*)d_out);
    out_convert<<<out_size/256, 256>>>((int*)d_out, (float*)d_out);
}